// round 1
// baseline (speedup 1.0000x reference)
#include <cuda_runtime.h>
#include <cstdint>

// ---------------- problem constants ----------------
#define Dd   1024
#define Hh   16
#define DHd  64
#define Bb   4
#define Nn   1024
#define Ee   (2*Dd + DHd)      // 2112
#define TOK  (Bb*Nn)           // 4096

// ---------------- scratch (device globals; no allocs allowed) ----------------
__device__ float g_M   [(size_t)Hh*Dd*Dd];     //  64 MB   M_h = Wq_h @ Wk_h^T
__device__ float g_t   [(size_t)Hh*TOK*Dd];    // 256 MB   t = x @ M_h      [h][b*N+n][j]
__device__ float g_Araw[(size_t)Bb*Hh*Nn*Nn];  // 256 MB   scores/probs     [b*H+h][n][m]
__device__ float g_v   [(size_t)Hh*TOK*DHd];   //  16 MB   v                [h][b*N+m][dh]
__device__ float g_sa  [(size_t)TOK*Dd];       //  16 MB   sa               [b*N+n][h*DH+dh]
__device__ float g_u   [Hh*Dd];
__device__ float g_w   [Hh*Dd];
__device__ float g_c   [Hh];
__device__ float g_rq  [Bb*Hh*Nn];
__device__ float g_rk  [Bb*Hh*Nn];

// ---------------- tf32 helpers ----------------
__device__ __forceinline__ uint32_t f2tf32(float f) {
    uint32_t u;
    asm("cvt.rna.tf32.f32 %0, %1;" : "=r"(u) : "f"(f));
    return u;
}

__device__ __forceinline__ void mma_tf32(float* d, const uint32_t* a, const uint32_t* b) {
    asm volatile(
        "mma.sync.aligned.m16n8k8.row.col.f32.tf32.tf32.f32 "
        "{%0,%1,%2,%3}, {%4,%5,%6,%7}, {%8,%9}, {%0,%1,%2,%3};\n"
        : "+f"(d[0]), "+f"(d[1]), "+f"(d[2]), "+f"(d[3])
        : "r"(a[0]), "r"(a[1]), "r"(a[2]), "r"(a[3]),
          "r"(b[0]), "r"(b[1]));
}

// ---------------- generic batched GEMM (tf32 tensor cores) ----------------
// C[z][m][n] = sum_k A[m,k] * B[k,n]  (+ bias[n])
// A elem at Ab[m*as_m + k*as_k], B elem at Bb[k*bs_k + n*bs_n], C at Cb[m*cs_m + n]
// batch z decomposed as zo = z/zdiv, zi = z%zdiv; per-operand offsets zo*so + zi*si.
struct GemmP {
    const float* A; const float* B; float* C; const float* bias;
    long long as_m, as_k, bs_k, bs_n, cs_m;
    long long a_so, a_si, b_so, b_si, c_so, c_si, bias_so, bias_si;
    int M, N, K, zdiv;
};

#define BM 128
#define BN 128
#define BK 32

__global__ __launch_bounds__(256) void gemm_tf32_kernel(GemmP p) {
    __shared__ uint32_t As[BK][BM + 1];
    __shared__ uint32_t Bs[BK][BN + 1];

    const int z  = blockIdx.z;
    const long long zo = z / p.zdiv;
    const long long zi = z % p.zdiv;

    const float* Ab = p.A + zo * p.a_so + zi * p.a_si;
    const float* Bv = p.B + zo * p.b_so + zi * p.b_si;
    float*       Cb = p.C + zo * p.c_so + zi * p.c_si;

    const int m0 = blockIdx.y * BM;
    const int n0 = blockIdx.x * BN;

    const int tid  = threadIdx.x;
    const int warp = tid >> 5;
    const int lane = tid & 31;
    const int wm   = (warp >> 2) * 64;   // warp grid 2 x 4 over 128 x 128
    const int wn   = (warp & 3)  * 32;
    const int grp  = lane >> 2;          // 0..7
    const int t4   = lane & 3;           // 0..3

    float acc[4][4][4];
#pragma unroll
    for (int i = 0; i < 4; i++)
#pragma unroll
        for (int j = 0; j < 4; j++)
#pragma unroll
            for (int r = 0; r < 4; r++) acc[i][j][r] = 0.f;

    const bool aKfast = (p.as_k == 1);
    const bool bKfast = (p.bs_k == 1);

    for (int k0 = 0; k0 < p.K; k0 += BK) {
        // ---- load A tile (BM x BK) ----
        if (aKfast) {
#pragma unroll
            for (int i = 0; i < 16; i++) {
                int idx = tid + i * 256;
                int k = idx & 31, m = idx >> 5;
                int gm = m0 + m;
                float v = (gm < p.M) ? __ldg(Ab + (long long)gm * p.as_m + (k0 + k)) : 0.f;
                As[k][m] = f2tf32(v);
            }
        } else {
#pragma unroll
            for (int i = 0; i < 16; i++) {
                int idx = tid + i * 256;
                int m = idx & 127, k = idx >> 7;
                int gm = m0 + m;
                float v = (gm < p.M) ? __ldg(Ab + (long long)gm * p.as_m + (long long)(k0 + k) * p.as_k) : 0.f;
                As[k][m] = f2tf32(v);
            }
        }
        // ---- load B tile (BK x BN) ----
        if (bKfast) {
#pragma unroll
            for (int i = 0; i < 16; i++) {
                int idx = tid + i * 256;
                int k = idx & 31, n = idx >> 5;
                int gn = n0 + n;
                float v = (gn < p.N) ? __ldg(Bv + (long long)gn * p.bs_n + (k0 + k)) : 0.f;
                Bs[k][n] = f2tf32(v);
            }
        } else {
#pragma unroll
            for (int i = 0; i < 16; i++) {
                int idx = tid + i * 256;
                int n = idx & 127, k = idx >> 7;
                int gn = n0 + n;
                float v = (gn < p.N) ? __ldg(Bv + (long long)(k0 + k) * p.bs_k + gn) : 0.f;
                Bs[k][n] = f2tf32(v);
            }
        }
        __syncthreads();

#pragma unroll
        for (int ks = 0; ks < 4; ks++) {
            uint32_t a[4][4];
            uint32_t b[4][2];
#pragma unroll
            for (int mt = 0; mt < 4; mt++) {
                int r = wm + mt * 16 + grp;
                a[mt][0] = As[ks * 8 + t4    ][r];
                a[mt][1] = As[ks * 8 + t4    ][r + 8];
                a[mt][2] = As[ks * 8 + t4 + 4][r];
                a[mt][3] = As[ks * 8 + t4 + 4][r + 8];
            }
#pragma unroll
            for (int nt = 0; nt < 4; nt++) {
                int c = wn + nt * 8 + grp;
                b[nt][0] = Bs[ks * 8 + t4    ][c];
                b[nt][1] = Bs[ks * 8 + t4 + 4][c];
            }
#pragma unroll
            for (int mt = 0; mt < 4; mt++)
#pragma unroll
                for (int nt = 0; nt < 4; nt++)
                    mma_tf32(acc[mt][nt], a[mt], b[nt]);
        }
        __syncthreads();
    }

    const float* biasb = nullptr;
    if (p.bias) biasb = p.bias + zo * p.bias_so + zi * p.bias_si;

#pragma unroll
    for (int mt = 0; mt < 4; mt++) {
#pragma unroll
        for (int nt = 0; nt < 4; nt++) {
            int r = m0 + wm + mt * 16 + grp;
            int c = n0 + wn + nt * 8 + t4 * 2;
#pragma unroll
            for (int rr = 0; rr < 2; rr++) {
                int row = r + rr * 8;
                if (row < p.M) {
#pragma unroll
                    for (int cc = 0; cc < 2; cc++) {
                        int col = c + cc;
                        if (col < p.N) {
                            float v = acc[mt][nt][rr * 2 + cc];
                            if (biasb) v += biasb[col];
                            Cb[(long long)row * p.cs_m + col] = v;
                        }
                    }
                }
            }
        }
    }
}

// ---------------- bias-correction prep kernels (exact handling of bkqv) ----------------
__global__ void prep_uw_kernel(const float* __restrict__ Wkqv, const float* __restrict__ bkqv,
                               float* __restrict__ u, float* __restrict__ w) {
    int gw = (blockIdx.x * blockDim.x + threadIdx.x) >> 5;
    if (gw >= Hh * Dd) return;
    int lane = threadIdx.x & 31;
    int h = gw >> 10;      // /Dd
    int i = gw & (Dd - 1);
    const float* row = Wkqv + ((long long)h * Dd + i) * Ee;
    const float* bh  = bkqv + (long long)h * Ee;
    float s1 = 0.f, s2 = 0.f;
    for (int e = lane; e < Dd; e += 32) {
        s1 += row[Dd + e] * bh[e];        // Wq[i,e] * bk[e]
        s2 += row[e]      * bh[Dd + e];   // Wk[i,e] * bq[e]
    }
#pragma unroll
    for (int o = 16; o > 0; o >>= 1) {
        s1 += __shfl_xor_sync(0xffffffffu, s1, o);
        s2 += __shfl_xor_sync(0xffffffffu, s2, o);
    }
    if (lane == 0) { u[gw] = s1; w[gw] = s2; }
}

__global__ void prep_c_kernel(const float* __restrict__ bkqv, float* __restrict__ c) {
    int h = threadIdx.x >> 5;
    if (h >= Hh) return;
    int lane = threadIdx.x & 31;
    const float* bh = bkqv + (long long)h * Ee;
    float s = 0.f;
    for (int e = lane; e < Dd; e += 32) s += bh[Dd + e] * bh[e];
#pragma unroll
    for (int o = 16; o > 0; o >>= 1) s += __shfl_xor_sync(0xffffffffu, s, o);
    if (lane == 0) c[h] = s;
}

__global__ void prep_rqrk_kernel(const float* __restrict__ x, const float* __restrict__ u,
                                 const float* __restrict__ w, float* __restrict__ rq,
                                 float* __restrict__ rk) {
    int gw = (blockIdx.x * blockDim.x + threadIdx.x) >> 5;
    if (gw >= TOK * Hh) return;
    int lane = threadIdx.x & 31;
    int h   = gw & (Hh - 1);
    int tok = gw >> 4;                     // b*N + n
    const float* xr = x + (long long)tok * Dd;
    const float* uh = u + h * Dd;
    const float* wh = w + h * Dd;
    float s1 = 0.f, s2 = 0.f;
    for (int i = lane; i < Dd; i += 32) {
        float xv = xr[i];
        s1 += xv * uh[i];
        s2 += xv * wh[i];
    }
#pragma unroll
    for (int o = 16; o > 0; o >>= 1) {
        s1 += __shfl_xor_sync(0xffffffffu, s1, o);
        s2 += __shfl_xor_sync(0xffffffffu, s2, o);
    }
    if (lane == 0) {
        int b = tok >> 10, n = tok & (Nn - 1);
        int z = b * Hh + h;
        rq[z * Nn + n] = s1;
        rk[z * Nn + n] = s2;
    }
}

// ---------------- causal softmax: A = softmax((raw + rq_n + rk_m + c_h)/32) ----------------
__global__ void softmax_kernel(float* __restrict__ A, const float* __restrict__ rq,
                               const float* __restrict__ rk, const float* __restrict__ cvec) {
    const int row = blockIdx.x;          // z*N + n, grid = B*H*N
    const int z = row >> 10;
    const int n = row & (Nn - 1);
    const int h = z & (Hh - 1);
    float* rp = A + (long long)z * Nn * Nn + (long long)n * Nn;
    const float* rkz = rk + z * Nn;
    const float addn = rq[z * Nn + n] + cvec[h];
    const int tid = threadIdx.x;

    float l[4];
    float mx = -1e30f;
#pragma unroll
    for (int i = 0; i < 4; i++) {
        int m = tid + i * 256;
        float v = (m <= n) ? (rp[m] + addn + rkz[m]) * 0.03125f : -1e30f;
        l[i] = v;
        mx = fmaxf(mx, v);
    }
    __shared__ float red[256];
    red[tid] = mx; __syncthreads();
#pragma unroll
    for (int s = 128; s > 0; s >>= 1) {
        if (tid < s) red[tid] = fmaxf(red[tid], red[tid + s]);
        __syncthreads();
    }
    mx = red[0]; __syncthreads();

    float sum = 0.f;
#pragma unroll
    for (int i = 0; i < 4; i++) {
        float e = (l[i] > -1e29f) ? __expf(l[i] - mx) : 0.f;
        l[i] = e;
        sum += e;
    }
    red[tid] = sum; __syncthreads();
#pragma unroll
    for (int s = 128; s > 0; s >>= 1) {
        if (tid < s) red[tid] += red[tid + s];
        __syncthreads();
    }
    const float inv = 1.f / red[0];
#pragma unroll
    for (int i = 0; i < 4; i++) rp[tid + i * 256] = l[i] * inv;
}

// ---------------- launch ----------------
extern "C" void kernel_launch(void* const* d_in, const int* in_sizes, int n_in,
                              void* d_out, int out_size) {
    const float* x    = (const float*)d_in[0];
    const float* Wkqv = (const float*)d_in[1];
    const float* bkqv = (const float*)d_in[2];
    const float* Wp   = (const float*)d_in[3];
    const float* bp   = (const float*)d_in[4];
    float* out = (float*)d_out;

    float *gM, *gt, *gA, *gv, *gsa, *gu, *gw, *gc, *grq, *grk;
    cudaGetSymbolAddress((void**)&gM,  g_M);
    cudaGetSymbolAddress((void**)&gt,  g_t);
    cudaGetSymbolAddress((void**)&gA,  g_Araw);
    cudaGetSymbolAddress((void**)&gv,  g_v);
    cudaGetSymbolAddress((void**)&gsa, g_sa);
    cudaGetSymbolAddress((void**)&gu,  g_u);
    cudaGetSymbolAddress((void**)&gw,  g_w);
    cudaGetSymbolAddress((void**)&gc,  g_c);
    cudaGetSymbolAddress((void**)&grq, g_rq);
    cudaGetSymbolAddress((void**)&grk, g_rk);

    // bias-correction prep (exact even though bkqv happens to be zeros)
    prep_uw_kernel<<<(Hh * Dd * 32 + 255) / 256, 256>>>(Wkqv, bkqv, gu, gw);
    prep_c_kernel<<<1, 512>>>(bkqv, gc);
    prep_rqrk_kernel<<<(TOK * Hh * 32 + 255) / 256, 256>>>(x, gu, gw, grq, grk);

    // K1: M_h = Wq_h @ Wk_h^T   (per head: 1024x1024x1024)
    {
        GemmP p{};
        p.A = Wkqv + Dd; p.as_m = Ee; p.as_k = 1;
        p.a_so = (long long)Dd * Ee; p.a_si = 0;
        p.B = Wkqv; p.bs_k = 1; p.bs_n = Ee;
        p.b_so = (long long)Dd * Ee; p.b_si = 0;
        p.C = gM; p.cs_m = Dd; p.c_so = (long long)Dd * Dd; p.c_si = 0;
        p.bias = nullptr; p.bias_so = 0; p.bias_si = 0;
        p.M = Dd; p.N = Dd; p.K = Dd; p.zdiv = 1;
        gemm_tf32_kernel<<<dim3(8, 8, Hh), 256>>>(p);
    }
    // K2: t_h = X @ M_h   (per head: 4096x1024x1024)
    {
        GemmP p{};
        p.A = x; p.as_m = Dd; p.as_k = 1; p.a_so = 0; p.a_si = 0;
        p.B = gM; p.bs_k = Dd; p.bs_n = 1;
        p.b_so = (long long)Dd * Dd; p.b_si = 0;
        p.C = gt; p.cs_m = Dd; p.c_so = (long long)TOK * Dd; p.c_si = 0;
        p.bias = nullptr; p.bias_so = 0; p.bias_si = 0;
        p.M = TOK; p.N = Dd; p.K = Dd; p.zdiv = 1;
        gemm_tf32_kernel<<<dim3(8, 32, Hh), 256>>>(p);
    }
    // K3: Araw[z][n][m] = t_h[b,n,:] . x[b,m,:]   (per b,h: 1024x1024x1024)
    {
        GemmP p{};
        p.A = gt; p.as_m = Dd; p.as_k = 1;
        p.a_so = (long long)Nn * Dd;      // b
        p.a_si = (long long)TOK * Dd;     // h
        p.B = x; p.bs_k = 1; p.bs_n = Dd;
        p.b_so = (long long)Nn * Dd; p.b_si = 0;
        p.C = gA; p.cs_m = Nn;
        p.c_so = (long long)Hh * Nn * Nn; p.c_si = (long long)Nn * Nn;
        p.bias = nullptr; p.bias_so = 0; p.bias_si = 0;
        p.M = Nn; p.N = Nn; p.K = Dd; p.zdiv = Hh;
        gemm_tf32_kernel<<<dim3(8, 8, Bb * Hh), 256>>>(p);
    }
    // softmax with causal mask + scale + bias corrections
    softmax_kernel<<<Bb * Hh * Nn, 256>>>(gA, grq, grk, gc);

    // K4: v_h = X @ Wv_h + bv_h   (per head: 4096x64x1024)
    {
        GemmP p{};
        p.A = x; p.as_m = Dd; p.as_k = 1; p.a_so = 0; p.a_si = 0;
        p.B = Wkqv + 2 * Dd; p.bs_k = Ee; p.bs_n = 1;
        p.b_so = (long long)Dd * Ee; p.b_si = 0;
        p.C = gv; p.cs_m = DHd; p.c_so = (long long)TOK * DHd; p.c_si = 0;
        p.bias = bkqv + 2 * Dd; p.bias_so = Ee; p.bias_si = 0;
        p.M = TOK; p.N = DHd; p.K = Dd; p.zdiv = 1;
        gemm_tf32_kernel<<<dim3(1, 32, Hh), 256>>>(p);
    }
    // K5: sa[b,n,h,:] = A[z] @ v[h,b]   (per b,h: 1024x64x1024)
    {
        GemmP p{};
        p.A = gA; p.as_m = Nn; p.as_k = 1;
        p.a_so = (long long)Hh * Nn * Nn; p.a_si = (long long)Nn * Nn;
        p.B = gv; p.bs_k = DHd; p.bs_n = 1;
        p.b_so = (long long)Nn * DHd;     // b
        p.b_si = (long long)TOK * DHd;    // h
        p.C = gsa; p.cs_m = Dd;
        p.c_so = (long long)Nn * Dd;      // b
        p.c_si = DHd;                     // h
        p.bias = nullptr; p.bias_so = 0; p.bias_si = 0;
        p.M = Nn; p.N = DHd; p.K = Nn; p.zdiv = Hh;
        gemm_tf32_kernel<<<dim3(1, 8, Bb * Hh), 256>>>(p);
    }
    // K6: out = sa @ Wp + bp   (4096x1024x1024)
    {
        GemmP p{};
        p.A = gsa; p.as_m = Dd; p.as_k = 1; p.a_so = 0; p.a_si = 0;
        p.B = Wp; p.bs_k = Dd; p.bs_n = 1; p.b_so = 0; p.b_si = 0;
        p.C = out; p.cs_m = Dd; p.c_so = 0; p.c_si = 0;
        p.bias = bp; p.bias_so = 0; p.bias_si = 0;
        p.M = TOK; p.N = Dd; p.K = Dd; p.zdiv = 1;
        gemm_tf32_kernel<<<dim3(8, 32, 1), 256>>>(p);
    }
}

// round 2
// speedup vs baseline: 3.4925x; 3.4925x over previous
#include <cuda_runtime.h>
#include <cstdint>

// ---------------- problem constants ----------------
#define Dd   1024
#define Hh   16
#define DHd  64
#define Bb   4
#define Nn   1024
#define Ee   (2*Dd + DHd)      // 2112
#define TOK  (Bb*Nn)           // 4096

// ---------------- scratch (device globals; no allocs allowed) ----------------
__device__ float g_M   [(size_t)Hh*Dd*Dd];     //  64 MB   M_h = Wq_h @ Wk_h^T
__device__ float g_t   [(size_t)Hh*TOK*Dd];    // 256 MB   t = x @ M_h      [h][b*N+n][j]
__device__ float g_Araw[(size_t)Bb*Hh*Nn*Nn];  // 256 MB   scores/probs     [b*H+h][n][m]
__device__ float g_v   [(size_t)Hh*TOK*DHd];   //  16 MB   v                [h][b*N+m][dh]
__device__ float g_sa  [(size_t)TOK*Dd];       //  16 MB   sa               [b*N+n][h*DH+dh]
__device__ float g_u   [Hh*Dd];
__device__ float g_w   [Hh*Dd];
__device__ float g_c   [Hh];
__device__ float g_rq  [Bb*Hh*Nn];
__device__ float g_rk  [Bb*Hh*Nn];

// ---------------- tf32 helpers ----------------
__device__ __forceinline__ uint32_t f2tf32(float f) {
    uint32_t u;
    asm("cvt.rna.tf32.f32 %0, %1;" : "=r"(u) : "f"(f));
    return u;
}

__device__ __forceinline__ void mma_tf32(float* d, const uint32_t* a, const uint32_t* b) {
    asm volatile(
        "mma.sync.aligned.m16n8k8.row.col.f32.tf32.tf32.f32 "
        "{%0,%1,%2,%3}, {%4,%5,%6,%7}, {%8,%9}, {%0,%1,%2,%3};\n"
        : "+f"(d[0]), "+f"(d[1]), "+f"(d[2]), "+f"(d[3])
        : "r"(a[0]), "r"(a[1]), "r"(a[2]), "r"(a[3]),
          "r"(b[0]), "r"(b[1]));
}

__device__ __forceinline__ void cpa16(float* dst, const float* src, bool full) {
    uint32_t d = (uint32_t)__cvta_generic_to_shared(dst);
    int sz = full ? 16 : 0;
    asm volatile("cp.async.cg.shared.global [%0], [%1], 16, %2;\n"
                 :: "r"(d), "l"(src), "r"(sz));
}
__device__ __forceinline__ void cp_commit() {
    asm volatile("cp.async.commit_group;\n");
}
template<int N>
__device__ __forceinline__ void cp_wait() {
    asm volatile("cp.async.wait_group %0;\n" :: "n"(N));
}

// ---------------- generic batched GEMM (tf32 tensor cores, cp.async 3-stage) ----
// C[z][m][n] = sum_k A[m,k] * B[k,n]  (+ bias[n])
// A is always [M,K] k-contiguous with row stride as_m.
// B: b_kcontig=1 -> B[n][k] k-contiguous, row stride bs_row (n rows)
//    b_kcontig=0 -> B[k][n] n-contiguous, row stride bs_row (k rows)
struct GemmP {
    const float* A; const float* B; float* C; const float* bias;
    int as_m, bs_row, cs_m;
    int b_kcontig;
    long long a_so, a_si, b_so, b_si, c_so, c_si, bias_so;
    int M, N, K, zdiv;
    int causal;   // skip CTAs fully above the diagonal (C[n][m], m>n)
    int klimit;   // K_eff = min(K, m0+BM)  (A rows n only need k=m <= n)
};

#define BM 128
#define BN 128
#define BK 32
#define ASTR 36     // A smem row stride (floats): bank-conflict-free pad
#define BSTR_KC 36  // B smem row stride, k-contig layout [n][k]
#define BSTR_NC 136 // B smem row stride, n-contig layout [k][n]
#define A_TILE (BM*ASTR)               // 4608 floats
#define B_TILE 4608                    // max(128*36, 32*136)=4608 floats
#define STAGES 3
#define SMEM_FLOATS (STAGES*(A_TILE + B_TILE))   // 27648 floats = 110592 B

__global__ __launch_bounds__(256) void gemm_tf32_kernel(GemmP p) {
    extern __shared__ float smem[];

    if (p.causal && ((int)blockIdx.x > (int)blockIdx.y)) return;

    const int z  = blockIdx.z;
    const long long zo = z / p.zdiv;
    const long long zi = z % p.zdiv;

    const float* Ab = p.A + zo * p.a_so + zi * p.a_si;
    const float* Bv = p.B + zo * p.b_so + zi * p.b_si;
    float*       Cb = p.C + zo * p.c_so + zi * p.c_si;

    const int m0 = blockIdx.y * BM;
    const int n0 = blockIdx.x * BN;

    const int tid  = threadIdx.x;
    const int warp = tid >> 5;
    const int lane = tid & 31;
    const int wm   = (warp >> 2) * 64;   // warp grid 2 x 4 over 128 x 128
    const int wn   = (warp & 3)  * 32;
    const int grp  = lane >> 2;          // 0..7
    const int t4   = lane & 3;           // 0..3

    const int K_eff = p.klimit ? min(p.K, m0 + BM) : p.K;
    const int nIter = K_eff / BK;

    // ---- per-thread loader coordinates ----
    // A tile: 128 rows x 8 chunks of 16B
    const int a_m  = tid >> 3;
    const int a_kc = (tid & 7) * 4;
    const float* a_src0 = Ab + (size_t)(m0 + a_m) * p.as_m + a_kc;
    // B k-contig: 128 n-rows x 8 chunks
    const int bk_n  = tid >> 3;
    const int bk_kc = (tid & 7) * 4;
    const float* bk_src0 = Bv + (size_t)(n0 + bk_n) * p.bs_row + bk_kc;
    // B n-contig: 32 k-rows x 32 chunks
    const int bn_k  = tid >> 5;
    const int bn_nc = (tid & 31) * 4;
    const bool bn_full = (n0 + bn_nc) < p.N;
    const float* bn_src0 = bn_full ? (Bv + (size_t)bn_k * p.bs_row + n0 + bn_nc) : Bv;

    const bool bkc = (p.b_kcontig != 0);

    // issue loads for stage st at k-offset k0
    auto load_tiles = [&](int st, int k0) {
        float* Asb = smem + st * A_TILE;
        {
            const float* src = a_src0 + k0;
            float* dst = Asb + a_m * ASTR + a_kc;
#pragma unroll
            for (int i = 0; i < 4; i++) {
                cpa16(dst, src, true);
                src += (size_t)32 * p.as_m;
                dst += 32 * ASTR;
            }
        }
        float* Bsb = smem + STAGES * A_TILE + st * B_TILE;
        if (bkc) {
            const float* src = bk_src0 + k0;
            float* dst = Bsb + bk_n * BSTR_KC + bk_kc;
#pragma unroll
            for (int i = 0; i < 4; i++) {
                cpa16(dst, src, true);
                src += (size_t)32 * p.bs_row;
                dst += 32 * BSTR_KC;
            }
        } else {
            const float* src = bn_src0 + (size_t)k0 * p.bs_row;
            float* dst = Bsb + bn_k * BSTR_NC + bn_nc;
#pragma unroll
            for (int i = 0; i < 4; i++) {
                cpa16(dst, src, bn_full);
                src += (size_t)8 * p.bs_row;
                dst += 8 * BSTR_NC;
            }
        }
        cp_commit();
    };

    float acc[4][4][4];
#pragma unroll
    for (int i = 0; i < 4; i++)
#pragma unroll
        for (int j = 0; j < 4; j++)
#pragma unroll
            for (int r = 0; r < 4; r++) acc[i][j][r] = 0.f;

    // prologue: prefetch 2 stages
    load_tiles(0, 0);
    load_tiles(1, BK);

    for (int it = 0; it < nIter; it++) {
        const int st = it % STAGES;
        if (it + 2 < nIter) {
            load_tiles((it + 2) % STAGES, (it + 2) * BK);
            cp_wait<2>();
        } else if (it + 1 < nIter) {
            cp_wait<1>();
        } else {
            cp_wait<0>();
        }
        __syncthreads();

        const float* Asb = smem + st * A_TILE;
        const float* Bsb = smem + STAGES * A_TILE + st * B_TILE;

#pragma unroll
        for (int ks = 0; ks < 4; ks++) {
            uint32_t a[4][4];
            uint32_t b[4][2];
#pragma unroll
            for (int mt = 0; mt < 4; mt++) {
                const float* ap = Asb + (wm + mt * 16 + grp) * ASTR + ks * 8 + t4;
                a[mt][0] = f2tf32(ap[0]);
                a[mt][1] = f2tf32(ap[8 * ASTR]);
                a[mt][2] = f2tf32(ap[4]);
                a[mt][3] = f2tf32(ap[8 * ASTR + 4]);
            }
            if (bkc) {
#pragma unroll
                for (int nt = 0; nt < 4; nt++) {
                    const float* bp = Bsb + (wn + nt * 8 + grp) * BSTR_KC + ks * 8 + t4;
                    b[nt][0] = f2tf32(bp[0]);
                    b[nt][1] = f2tf32(bp[4]);
                }
            } else {
#pragma unroll
                for (int nt = 0; nt < 4; nt++) {
                    const float* bp = Bsb + (ks * 8 + t4) * BSTR_NC + wn + nt * 8 + grp;
                    b[nt][0] = f2tf32(bp[0]);
                    b[nt][1] = f2tf32(bp[4 * BSTR_NC]);
                }
            }
#pragma unroll
            for (int mt = 0; mt < 4; mt++)
#pragma unroll
                for (int nt = 0; nt < 4; nt++)
                    mma_tf32(acc[mt][nt], a[mt], b[nt]);
        }
        __syncthreads();
    }

    const float* biasb = nullptr;
    if (p.bias) biasb = p.bias + zo * p.bias_so;

#pragma unroll
    for (int mt = 0; mt < 4; mt++) {
#pragma unroll
        for (int nt = 0; nt < 4; nt++) {
            int c = n0 + wn + nt * 8 + t4 * 2;
            if (c >= p.N) continue;
            float b0 = 0.f, b1 = 0.f;
            if (biasb) { b0 = biasb[c]; b1 = biasb[c + 1]; }
#pragma unroll
            for (int rr = 0; rr < 2; rr++) {
                int row = m0 + wm + mt * 16 + grp + rr * 8;
                float2 v2;
                v2.x = acc[mt][nt][rr * 2]     + b0;
                v2.y = acc[mt][nt][rr * 2 + 1] + b1;
                *reinterpret_cast<float2*>(Cb + (size_t)row * p.cs_m + c) = v2;
            }
        }
    }
}

// ---------------- bias-correction prep kernels (exact handling of bkqv) ----------------
__global__ void prep_uw_kernel(const float* __restrict__ Wkqv, const float* __restrict__ bkqv,
                               float* __restrict__ u, float* __restrict__ w) {
    int gw = (blockIdx.x * blockDim.x + threadIdx.x) >> 5;
    if (gw >= Hh * Dd) return;
    int lane = threadIdx.x & 31;
    int h = gw >> 10;
    int i = gw & (Dd - 1);
    const float* row = Wkqv + ((long long)h * Dd + i) * Ee;
    const float* bh  = bkqv + (long long)h * Ee;
    float s1 = 0.f, s2 = 0.f;
    for (int e = lane; e < Dd; e += 32) {
        s1 += row[Dd + e] * bh[e];
        s2 += row[e]      * bh[Dd + e];
    }
#pragma unroll
    for (int o = 16; o > 0; o >>= 1) {
        s1 += __shfl_xor_sync(0xffffffffu, s1, o);
        s2 += __shfl_xor_sync(0xffffffffu, s2, o);
    }
    if (lane == 0) { u[gw] = s1; w[gw] = s2; }
}

__global__ void prep_c_kernel(const float* __restrict__ bkqv, float* __restrict__ c) {
    int h = threadIdx.x >> 5;
    if (h >= Hh) return;
    int lane = threadIdx.x & 31;
    const float* bh = bkqv + (long long)h * Ee;
    float s = 0.f;
    for (int e = lane; e < Dd; e += 32) s += bh[Dd + e] * bh[e];
#pragma unroll
    for (int o = 16; o > 0; o >>= 1) s += __shfl_xor_sync(0xffffffffu, s, o);
    if (lane == 0) c[h] = s;
}

__global__ void prep_rqrk_kernel(const float* __restrict__ x, const float* __restrict__ u,
                                 const float* __restrict__ w, float* __restrict__ rq,
                                 float* __restrict__ rk) {
    int gw = (blockIdx.x * blockDim.x + threadIdx.x) >> 5;
    if (gw >= TOK * Hh) return;
    int lane = threadIdx.x & 31;
    int h   = gw & (Hh - 1);
    int tok = gw >> 4;
    const float* xr = x + (long long)tok * Dd;
    const float* uh = u + h * Dd;
    const float* wh = w + h * Dd;
    float s1 = 0.f, s2 = 0.f;
    for (int i = lane; i < Dd; i += 32) {
        float xv = xr[i];
        s1 += xv * uh[i];
        s2 += xv * wh[i];
    }
#pragma unroll
    for (int o = 16; o > 0; o >>= 1) {
        s1 += __shfl_xor_sync(0xffffffffu, s1, o);
        s2 += __shfl_xor_sync(0xffffffffu, s2, o);
    }
    if (lane == 0) {
        int b = tok >> 10, n = tok & (Nn - 1);
        int z = b * Hh + h;
        rq[z * Nn + n] = s1;
        rk[z * Nn + n] = s2;
    }
}

// ---------------- causal softmax: A = softmax((raw + rq_n + rk_m + c_h)/32) ----------------
__global__ void softmax_kernel(float* __restrict__ A, const float* __restrict__ rq,
                               const float* __restrict__ rk, const float* __restrict__ cvec) {
    const int row = blockIdx.x;
    const int z = row >> 10;
    const int n = row & (Nn - 1);
    const int h = z & (Hh - 1);
    float* rp = A + (long long)z * Nn * Nn + (long long)n * Nn;
    const float* rkz = rk + z * Nn;
    const float addn = rq[z * Nn + n] + cvec[h];
    const int tid = threadIdx.x;

    float l[4];
    float mx = -1e30f;
#pragma unroll
    for (int i = 0; i < 4; i++) {
        int m = tid + i * 256;
        float v = (m <= n) ? (rp[m] + addn + rkz[m]) * 0.03125f : -1e30f;
        l[i] = v;
        mx = fmaxf(mx, v);
    }
    __shared__ float red[256];
    red[tid] = mx; __syncthreads();
#pragma unroll
    for (int s = 128; s > 0; s >>= 1) {
        if (tid < s) red[tid] = fmaxf(red[tid], red[tid + s]);
        __syncthreads();
    }
    mx = red[0]; __syncthreads();

    float sum = 0.f;
#pragma unroll
    for (int i = 0; i < 4; i++) {
        float e = (l[i] > -1e29f) ? __expf(l[i] - mx) : 0.f;
        l[i] = e;
        sum += e;
    }
    red[tid] = sum; __syncthreads();
#pragma unroll
    for (int s = 128; s > 0; s >>= 1) {
        if (tid < s) red[tid] += red[tid + s];
        __syncthreads();
    }
    const float inv = 1.f / red[0];
#pragma unroll
    for (int i = 0; i < 4; i++) rp[tid + i * 256] = l[i] * inv;
}

// ---------------- launch ----------------
extern "C" void kernel_launch(void* const* d_in, const int* in_sizes, int n_in,
                              void* d_out, int out_size) {
    const float* x    = (const float*)d_in[0];
    const float* Wkqv = (const float*)d_in[1];
    const float* bkqv = (const float*)d_in[2];
    const float* Wp   = (const float*)d_in[3];
    const float* bp   = (const float*)d_in[4];
    float* out = (float*)d_out;

    float *gM, *gt, *gA, *gv, *gsa, *gu, *gw, *gc, *grq, *grk;
    cudaGetSymbolAddress((void**)&gM,  g_M);
    cudaGetSymbolAddress((void**)&gt,  g_t);
    cudaGetSymbolAddress((void**)&gA,  g_Araw);
    cudaGetSymbolAddress((void**)&gv,  g_v);
    cudaGetSymbolAddress((void**)&gsa, g_sa);
    cudaGetSymbolAddress((void**)&gu,  g_u);
    cudaGetSymbolAddress((void**)&gw,  g_w);
    cudaGetSymbolAddress((void**)&gc,  g_c);
    cudaGetSymbolAddress((void**)&grq, g_rq);
    cudaGetSymbolAddress((void**)&grk, g_rk);

    static int smem_set = 0;
    if (!smem_set) {
        cudaFuncSetAttribute(gemm_tf32_kernel,
                             cudaFuncAttributeMaxDynamicSharedMemorySize,
                             SMEM_FLOATS * 4);
        smem_set = 1;
    }
    const int SMEM_B = SMEM_FLOATS * 4;

    // bias-correction prep (exact even though bkqv happens to be zeros)
    prep_uw_kernel<<<(Hh * Dd * 32 + 255) / 256, 256>>>(Wkqv, bkqv, gu, gw);
    prep_c_kernel<<<1, 512>>>(bkqv, gc);
    prep_rqrk_kernel<<<(TOK * Hh * 32 + 255) / 256, 256>>>(x, gu, gw, grq, grk);

    // K1: M_h = Wq_h @ Wk_h^T   (per head: 1024x1024x1024)
    {
        GemmP p{};
        p.A = Wkqv + Dd; p.as_m = Ee; p.a_so = (long long)Dd * Ee; p.a_si = 0;
        p.B = Wkqv; p.b_kcontig = 1; p.bs_row = Ee;
        p.b_so = (long long)Dd * Ee; p.b_si = 0;
        p.C = gM; p.cs_m = Dd; p.c_so = (long long)Dd * Dd; p.c_si = 0;
        p.bias = nullptr; p.bias_so = 0;
        p.M = Dd; p.N = Dd; p.K = Dd; p.zdiv = 1; p.causal = 0; p.klimit = 0;
        gemm_tf32_kernel<<<dim3(8, 8, Hh), 256, SMEM_B>>>(p);
    }
    // K2: t_h = X @ M_h   (per head: 4096x1024x1024)
    {
        GemmP p{};
        p.A = x; p.as_m = Dd; p.a_so = 0; p.a_si = 0;
        p.B = gM; p.b_kcontig = 0; p.bs_row = Dd;
        p.b_so = (long long)Dd * Dd; p.b_si = 0;
        p.C = gt; p.cs_m = Dd; p.c_so = (long long)TOK * Dd; p.c_si = 0;
        p.bias = nullptr; p.bias_so = 0;
        p.M = TOK; p.N = Dd; p.K = Dd; p.zdiv = 1; p.causal = 0; p.klimit = 0;
        gemm_tf32_kernel<<<dim3(8, 32, Hh), 256, SMEM_B>>>(p);
    }
    // K3: Araw[z][n][m] = t_h[b,n,:] . x[b,m,:]   (per b,h: 1024x1024x1024, causal)
    {
        GemmP p{};
        p.A = gt; p.as_m = Dd;
        p.a_so = (long long)Nn * Dd;      // b
        p.a_si = (long long)TOK * Dd;     // h
        p.B = x; p.b_kcontig = 1; p.bs_row = Dd;
        p.b_so = (long long)Nn * Dd; p.b_si = 0;
        p.C = gA; p.cs_m = Nn;
        p.c_so = (long long)Hh * Nn * Nn; p.c_si = (long long)Nn * Nn;
        p.bias = nullptr; p.bias_so = 0;
        p.M = Nn; p.N = Nn; p.K = Dd; p.zdiv = Hh; p.causal = 1; p.klimit = 0;
        gemm_tf32_kernel<<<dim3(8, 8, Bb * Hh), 256, SMEM_B>>>(p);
    }
    // softmax with causal mask + scale + bias corrections
    softmax_kernel<<<Bb * Hh * Nn, 256>>>(gA, grq, grk, gc);

    // K4: v_h = X @ Wv_h + bv_h   (per head: 4096x64x1024)
    {
        GemmP p{};
        p.A = x; p.as_m = Dd; p.a_so = 0; p.a_si = 0;
        p.B = Wkqv + 2 * Dd; p.b_kcontig = 0; p.bs_row = Ee;
        p.b_so = (long long)Dd * Ee; p.b_si = 0;
        p.C = gv; p.cs_m = DHd; p.c_so = (long long)TOK * DHd; p.c_si = 0;
        p.bias = bkqv + 2 * Dd; p.bias_so = Ee;
        p.M = TOK; p.N = DHd; p.K = Dd; p.zdiv = 1; p.causal = 0; p.klimit = 0;
        gemm_tf32_kernel<<<dim3(1, 32, Hh), 256, SMEM_B>>>(p);
    }
    // K5: sa[b,n,h,:] = A[z] @ v[h,b]   (per b,h: 1024x64x1024, K limited by causality)
    {
        GemmP p{};
        p.A = gA; p.as_m = Nn;
        p.a_so = (long long)Hh * Nn * Nn; p.a_si = (long long)Nn * Nn;
        p.B = gv; p.b_kcontig = 0; p.bs_row = DHd;
        p.b_so = (long long)Nn * DHd;     // b
        p.b_si = (long long)TOK * DHd;    // h
        p.C = gsa; p.cs_m = Dd;
        p.c_so = (long long)Nn * Dd;      // b
        p.c_si = DHd;                     // h
        p.bias = nullptr; p.bias_so = 0;
        p.M = Nn; p.N = DHd; p.K = Nn; p.zdiv = Hh; p.causal = 0; p.klimit = 1;
        gemm_tf32_kernel<<<dim3(1, 8, Bb * Hh), 256, SMEM_B>>>(p);
    }
    // K6: out = sa @ Wp + bp   (4096x1024x1024)
    {
        GemmP p{};
        p.A = gsa; p.as_m = Dd; p.a_so = 0; p.a_si = 0;
        p.B = Wp; p.b_kcontig = 0; p.bs_row = Dd; p.b_so = 0; p.b_si = 0;
        p.C = out; p.cs_m = Dd; p.c_so = 0; p.c_si = 0;
        p.bias = bp; p.bias_so = 0;
        p.M = TOK; p.N = Dd; p.K = Dd; p.zdiv = 1; p.causal = 0; p.klimit = 0;
        gemm_tf32_kernel<<<dim3(8, 32, 1), 256, SMEM_B>>>(p);
    }
}